// round 8
// baseline (speedup 1.0000x reference)
#include <cuda_runtime.h>
#include <cstdint>

// ---------------------------------------------------------------------------
// ClockworkGRU:
//   Phase A: proj[z] = x @ Wz + bz for z in {W, Wr, Wz}   (3x SGEMM, fp32)
//   Phase B: scan — 4-CTA cluster per PAIR of batch elements, column-split.
//            v8: NO SMEM atomics — every k-segment task writes a private
//            partial slot; reduction happens at the sigmoid points.
// ---------------------------------------------------------------------------

#define GM 32768
#define GK 512
#define GN 512
#define SEQ_LEN 512
#define NBATCH 64

__device__ float g_proj[3ull * GM * GN];

// per-block task/seg tables (r: i-th block; depths r/z = {16,64,128,128}, h = {16,64,64,64})
__constant__ int c_TR[4]  = {64, 64, 72, 128};   // r tasks  = quads * segs
__constant__ int c_TZ[4]  = {64, 32, 24, 32};    // z tasks
__constant__ int c_TH[4]  = {64, 32, 48, 64};    // hn tasks
__constant__ int c_SR[4]  = {8, 4, 3, 4};        // r segs
__constant__ int c_SZ[4]  = {8, 4, 3, 4};        // z segs
__constant__ int c_SH[4]  = {8, 4, 6, 8};        // h segs
__constant__ int c_RPB[4] = {0, 512, 1024, 1600};
__constant__ int c_ZPB[4] = {0, 512, 768, 960};
__constant__ int c_HPB[4] = {0, 512, 768, 1152};
__constant__ int c_OFF[4] = {0, 128, 384, 768};

// ---------------- helpers ----------------------------------------------------
__device__ __forceinline__ unsigned long long pack2(float x, float y) {
    unsigned long long r;
    asm("mov.b64 %0, {%1, %2};" : "=l"(r) : "f"(x), "f"(y));
    return r;
}
__device__ __forceinline__ void fma2(unsigned long long& d,
                                     unsigned long long a,
                                     unsigned long long b) {
    asm("fma.rn.f32x2 %0, %1, %2, %0;" : "+l"(d) : "l"(a), "l"(b));
}
__device__ __forceinline__ float2 unpack2(unsigned long long v) {
    float2 r;
    asm("mov.b64 {%0, %1}, %2;" : "=f"(r.x), "=f"(r.y) : "l"(v));
    return r;
}
__device__ __forceinline__ float sigmoidf_(float x) {
    return 1.0f / (1.0f + __expf(-x));
}
__device__ __forceinline__ uint32_t smem_u32(const void* p) {
    return (uint32_t)__cvta_generic_to_shared(p);
}
__device__ __forceinline__ uint32_t mapa_u32(uint32_t addr, uint32_t rank) {
    uint32_t r;
    asm("mapa.shared::cluster.u32 %0, %1, %2;" : "=r"(r) : "r"(addr), "r"(rank));
    return r;
}
__device__ __forceinline__ void st_cluster_b64(uint32_t a, float x, float y) {
    unsigned long long v = pack2(x, y);
    asm volatile("st.shared::cluster.b64 [%0], %1;" :: "r"(a), "l"(v) : "memory");
}
#define CLUSTER_SYNC() do {                                           \
    asm volatile("barrier.cluster.arrive.aligned;" ::: "memory");     \
    asm volatile("barrier.cluster.wait.aligned;"   ::: "memory");     \
} while (0)

// ---------------------------------------------------------------------------
// GEMM (unchanged — ~0.95 ms)
// ---------------------------------------------------------------------------
#define BM 128
#define BN 128
#define BKK 8

__global__ void __launch_bounds__(256) gemm3_kernel(
    const float* __restrict__ A,
    const float* __restrict__ W0, const float* __restrict__ b0,
    const float* __restrict__ W1, const float* __restrict__ b1,
    const float* __restrict__ W2, const float* __restrict__ b2)
{
    __shared__ float As[BKK][BM];
    __shared__ float Bs[BKK][BN];

    const int z = blockIdx.z;
    const float* W    = (z == 0) ? W0 : (z == 1 ? W1 : W2);
    const float* bias = (z == 0) ? b0 : (z == 1 ? b1 : b2);
    float* C = g_proj + (size_t)z * GM * GN;

    const int m0 = blockIdx.y * BM;
    const int n0 = blockIdx.x * BN;
    const int tid = threadIdx.x;

    const int a_row = tid >> 1;
    const int a_k   = (tid & 1) * 4;
    const int b_row = tid >> 5;
    const int b_col = (tid & 31) * 4;

    const int warp = tid >> 5;
    const int lane = tid & 31;
    const int row0 = (warp & 3) * 32 + (lane & 3) * 8;
    const int col0 = (warp >> 2) * 64 + (lane >> 2) * 8;

    unsigned long long acc[8][4];
#pragma unroll
    for (int i = 0; i < 8; i++)
#pragma unroll
        for (int j = 0; j < 4; j++) acc[i][j] = 0ull;

    const float* Aptr = A + (size_t)(m0 + a_row) * GK + a_k;
    const float* Wptr = W + (size_t)b_row * GN + n0 + b_col;

    float4 ra = *(const float4*)Aptr;
    float4 rb = *(const float4*)Wptr;

    const int KT = GK / BKK;
    for (int kt = 0; kt < KT; kt++) {
        As[a_k + 0][a_row] = ra.x;
        As[a_k + 1][a_row] = ra.y;
        As[a_k + 2][a_row] = ra.z;
        As[a_k + 3][a_row] = ra.w;
        *(float4*)&Bs[b_row][b_col] = rb;
        __syncthreads();

        if (kt + 1 < KT) {
            ra = *(const float4*)(Aptr + (kt + 1) * BKK);
            rb = *(const float4*)(Wptr + (size_t)(kt + 1) * BKK * GN);
        }

#pragma unroll
        for (int k = 0; k < BKK; k++) {
            float4 a0 = *(const float4*)&As[k][row0];
            float4 a1 = *(const float4*)&As[k][row0 + 4];
            ulonglong2 bq0 = *(const ulonglong2*)&Bs[k][col0];
            ulonglong2 bq1 = *(const ulonglong2*)&Bs[k][col0 + 4];
            unsigned long long av[8];
            av[0] = pack2(a0.x, a0.x); av[1] = pack2(a0.y, a0.y);
            av[2] = pack2(a0.z, a0.z); av[3] = pack2(a0.w, a0.w);
            av[4] = pack2(a1.x, a1.x); av[5] = pack2(a1.y, a1.y);
            av[6] = pack2(a1.z, a1.z); av[7] = pack2(a1.w, a1.w);
#pragma unroll
            for (int i = 0; i < 8; i++) {
                fma2(acc[i][0], av[i], bq0.x);
                fma2(acc[i][1], av[i], bq0.y);
                fma2(acc[i][2], av[i], bq1.x);
                fma2(acc[i][3], av[i], bq1.y);
            }
        }
        __syncthreads();
    }

    float bb[8];
#pragma unroll
    for (int j = 0; j < 8; j++) bb[j] = bias[n0 + col0 + j];

#pragma unroll
    for (int i = 0; i < 8; i++) {
        float o[8];
#pragma unroll
        for (int jp = 0; jp < 4; jp++) {
            float2 v = unpack2(acc[i][jp]);
            o[2 * jp]     = v.x + bb[2 * jp];
            o[2 * jp + 1] = v.y + bb[2 * jp + 1];
        }
        size_t base = (size_t)(m0 + row0 + i) * GN + n0 + col0;
        *(float4*)&C[base]     = make_float4(o[0], o[1], o[2], o[3]);
        *(float4*)&C[base + 4] = make_float4(o[4], o[5], o[6], o[7]);
    }
}

// ---------------------------------------------------------------------------
// dots: 4 cols x 2 rows
// ---------------------------------------------------------------------------

// global, KSEG-deep, double-buffered 8+8, 2 rows
template<int KSEG>
__device__ __forceinline__ void dot_g42(const float* __restrict__ w, int stride,
                                        const float* __restrict__ h0,
                                        const float* __restrict__ h1,
                                        float* a0, float* a1)
{
    float4 A[8], B[8];
#pragma unroll
    for (int r = 0; r < 8; r++) A[r] = *(const float4*)(w + (size_t)r * stride);
#pragma unroll
    for (int kb = 0; kb < KSEG; kb += 16) {
#pragma unroll
        for (int r = 0; r < 8; r++)
            B[r] = *(const float4*)(w + (size_t)(kb + 8 + r) * stride);
#pragma unroll
        for (int r = 0; r < 8; r++) {
            float x0 = h0[kb + r], x1 = h1[kb + r];
            a0[0] = fmaf(x0, A[r].x, a0[0]); a0[1] = fmaf(x0, A[r].y, a0[1]);
            a0[2] = fmaf(x0, A[r].z, a0[2]); a0[3] = fmaf(x0, A[r].w, a0[3]);
            a1[0] = fmaf(x1, A[r].x, a1[0]); a1[1] = fmaf(x1, A[r].y, a1[1]);
            a1[2] = fmaf(x1, A[r].z, a1[2]); a1[3] = fmaf(x1, A[r].w, a1[3]);
        }
        if (kb + 16 < KSEG) {
#pragma unroll
            for (int r = 0; r < 8; r++)
                A[r] = *(const float4*)(w + (size_t)(kb + 16 + r) * stride);
        }
#pragma unroll
        for (int r = 0; r < 8; r++) {
            float x0 = h0[kb + 8 + r], x1 = h1[kb + 8 + r];
            a0[0] = fmaf(x0, B[r].x, a0[0]); a0[1] = fmaf(x0, B[r].y, a0[1]);
            a0[2] = fmaf(x0, B[r].z, a0[2]); a0[3] = fmaf(x0, B[r].w, a0[3]);
            a1[0] = fmaf(x1, B[r].x, a1[0]); a1[1] = fmaf(x1, B[r].y, a1[1]);
            a1[2] = fmaf(x1, B[r].z, a1[2]); a1[3] = fmaf(x1, B[r].w, a1[3]);
        }
    }
}

// smem dot, KSEG deep, stride STR, 2 rows
template<int KSEG, int STR>
__device__ __forceinline__ void dot_s42(const float* __restrict__ w,
                                        const float* __restrict__ h0,
                                        const float* __restrict__ h1,
                                        float* a0, float* a1)
{
#pragma unroll
    for (int k = 0; k < KSEG; k++) {
        float4 ww = *(const float4*)&w[k * STR];
        float x0 = h0[k], x1 = h1[k];
        a0[0] = fmaf(x0, ww.x, a0[0]); a0[1] = fmaf(x0, ww.y, a0[1]);
        a0[2] = fmaf(x0, ww.z, a0[2]); a0[3] = fmaf(x0, ww.w, a0[3]);
        a1[0] = fmaf(x1, ww.x, a1[0]); a1[1] = fmaf(x1, ww.y, a1[1]);
        a1[2] = fmaf(x1, ww.z, a1[2]); a1[3] = fmaf(x1, ww.w, a1[3]);
    }
}

// ---------------------------------------------------------------------------
__global__ void __launch_bounds__(512, 1) __cluster_dims__(4, 1, 1)
scan_kernel(
    const float* __restrict__ ch0, const float* __restrict__ cr0, const float* __restrict__ cz0,
    const float* __restrict__ ch1, const float* __restrict__ cr1, const float* __restrict__ cz1,
    const float* __restrict__ ch2, const float* __restrict__ cr2, const float* __restrict__ cz2,
    const float* __restrict__ ch3, const float* __restrict__ cr3, const float* __restrict__ cz3,
    float* __restrict__ out)
{
    extern __shared__ float smem[];
    float* h_s   = smem;              // 2 x 512
    float* rh_s  = smem + 1024;       // 2 x 1280
    float* rp    = smem + 3584;       // 2624 r partials
    float* zp    = smem + 6208;       // 1216 z partials
    float* hp    = smem + 7424;       // 1664 hn partials
    float* cr0_s = smem + 9088;       // 128 x 32
    float* cz0_s = smem + 13184;      // 128 x 32
    float* ch0_s = smem + 17280;      // 128 x 32
    float* cr1_s = smem + 21376;      // 256 x 64
    float* cz1_s = smem + 37760;      // 256 x 32
    float* ch1_s = smem + 45952;      // 256 x 32  (end 54144)

    const int rank = blockIdx.x & 3;
    const int bp   = blockIdx.x >> 2;
    const int tid  = threadIdx.x;

    // ---- preload own-column slices of block-0 and block-1 matrices ---------
    for (int i = tid; i < 1024; i += 512) {            // 128x32 slices
        const int row = i >> 3, c4 = (i & 7) * 4;
        const int src = row * 128 + rank * 32 + c4;
        const int dst = row * 32 + c4;
        *(float4*)&cr0_s[dst] = *(const float4*)&cr0[src];
        *(float4*)&cz0_s[dst] = *(const float4*)&cz0[src];
        *(float4*)&ch0_s[dst] = *(const float4*)&ch0[src];
    }
    for (int i = tid; i < 4096; i += 512) {            // cr1 256x64
        const int row = i >> 4, c4 = (i & 15) * 4;
        *(float4*)&cr1_s[row * 64 + c4] =
            *(const float4*)&cr1[row * 256 + rank * 64 + c4];
    }
    for (int i = tid; i < 2048; i += 512) {            // cz1/ch1 256x32
        const int row = i >> 3, c4 = (i & 7) * 4;
        *(float4*)&cz1_s[row * 32 + c4] =
            *(const float4*)&cz1[row * 128 + rank * 32 + c4];
        *(float4*)&ch1_s[row * 32 + c4] =
            *(const float4*)&ch1[row * 128 + rank * 32 + c4];
    }
    h_s[tid] = 0.0f; h_s[512 + tid] = 0.0f;
    __syncthreads();
    CLUSTER_SYNC();

    uint32_t peer_rh[3], peer_h[3];
    {
        int p = 0;
        for (int r = 0; r < 4; r++) {
            if (r == rank) continue;
            peer_rh[p] = mapa_u32(smem_u32(rh_s), (uint32_t)r);
            peer_h[p]  = mapa_u32(smem_u32(h_s),  (uint32_t)r);
            p++;
        }
    }

    const float* xt  = g_proj;
    const float* xrt = g_proj + (size_t)GM * GN;
    const float* xzt = g_proj + 2ull * GM * GN;

    for (int t = 0; t < SEQ_LEN; t++) {
        const bool a1 = (t & 1) == 0, a2 = (t & 3) == 0, a3 = (t & 7) == 0;
        int act[4]; int na = 0;
        act[na++] = 0;
        if (a1) act[na++] = 1;
        if (a2) act[na++] = 2;
        if (a3) act[na++] = 3;

        const size_t xr0 = ((size_t)(bp * 2 + 0) * SEQ_LEN + t) * GN;
        const size_t xr1 = ((size_t)(bp * 2 + 1) * SEQ_LEN + t) * GN;

        // ================= pass 1: r-dots + z-dots → private partials =======
        int total1 = 0;
        for (int a = 0; a < na; a++) total1 += c_TR[act[a]] + c_TZ[act[a]];

        for (int task = tid; task < total1; task += 512) {
            int tk = task;
            int i = 0; bool isR = true;
            for (int a = 0; a < na; a++) {
                const int ii = act[a];
                if (tk < c_TR[ii]) { i = ii; isR = true; break; }
                tk -= c_TR[ii];
                if (tk < c_TZ[ii]) { i = ii; isR = false; break; }
                tk -= c_TZ[ii];
            }

            float A0[4] = {0,0,0,0}, A1[4] = {0,0,0,0};
            int seg, c, colsP, pbase;

            if (isR) {
                if (i == 0) {
                    const int q = tk & 7; seg = tk >> 3; c = q * 4;
                    dot_s42<16, 32>(cr0_s + seg * 16 * 32 + c,
                                    h_s + seg * 16, h_s + 512 + seg * 16, A0, A1);
                    colsP = 32;
                } else if (i == 1) {
                    const int q = tk & 15; seg = tk >> 4; c = q * 4;
                    dot_s42<64, 64>(cr1_s + seg * 64 * 64 + c,
                                    h_s + seg * 64, h_s + 512 + seg * 64, A0, A1);
                    colsP = 64;
                } else if (i == 2) {
                    const int q = tk % 24; seg = tk / 24; c = q * 4;
                    dot_g42<128>(cr2 + (size_t)(seg * 128) * 384 + rank * 96 + c,
                                 384, h_s + seg * 128, h_s + 512 + seg * 128,
                                 A0, A1);
                    colsP = 96;
                } else {
                    const int q = tk & 31; seg = tk >> 5; c = q * 4;
                    dot_g42<128>(cr3 + (size_t)(seg * 128) * 512 + rank * 128 + c,
                                 512, h_s + seg * 128, h_s + 512 + seg * 128,
                                 A0, A1);
                    colsP = 128;
                }
                if (seg == 0) {
                    const int j = rank * colsP + c;
                    float4 B0 = *(const float4*)&xrt[xr0 + j];
                    float4 B1 = *(const float4*)&xrt[xr1 + j];
                    A0[0] += B0.x; A0[1] += B0.y; A0[2] += B0.z; A0[3] += B0.w;
                    A1[0] += B1.x; A1[1] += B1.y; A1[2] += B1.z; A1[3] += B1.w;
                }
                pbase = c_RPB[i];
            } else {
                const int q = tk & 7; seg = tk >> 3; c = q * 4;
                const int lc = rank * 32 + c;
                if (i == 0) {
                    dot_s42<16, 32>(cz0_s + seg * 16 * 32 + c,
                                    h_s + seg * 16, h_s + 512 + seg * 16, A0, A1);
                } else if (i == 1) {
                    dot_s42<64, 32>(cz1_s + seg * 64 * 32 + c,
                                    h_s + seg * 64, h_s + 512 + seg * 64, A0, A1);
                } else if (i == 2) {
                    dot_g42<128>(cz2 + (size_t)(seg * 128) * 128 + lc, 128,
                                 h_s + seg * 128, h_s + 512 + seg * 128, A0, A1);
                } else {
                    dot_g42<128>(cz3 + (size_t)(seg * 128) * 128 + lc, 128,
                                 h_s + seg * 128, h_s + 512 + seg * 128, A0, A1);
                }
                if (seg == 0) {
                    const int gc = (i << 7) + lc;
                    float4 B0 = *(const float4*)&xzt[xr0 + gc];
                    float4 B1 = *(const float4*)&xzt[xr1 + gc];
                    A0[0] += B0.x; A0[1] += B0.y; A0[2] += B0.z; A0[3] += B0.w;
                    A1[0] += B1.x; A1[1] += B1.y; A1[2] += B1.z; A1[3] += B1.w;
                }
                colsP = 32;
                pbase = c_ZPB[i];
            }
            float* P = (isR ? rp : zp) + pbase + (seg * 2) * colsP + c;
            *(float4*)P             = make_float4(A0[0], A0[1], A0[2], A0[3]);
            *(float4*)(P + colsP)   = make_float4(A1[0], A1[1], A1[2], A1[3]);
        }
        __syncthreads();

        // ================= pass 2: reduce r, rh = sig(r)*h, exchange ========
        {
            int pcount[4]; int npairs = 0;
            for (int a = 0; a < na; a++) {
                pcount[a] = (act[a] + 1) * 16;
                npairs += pcount[a];
            }
            for (int s = tid; s < 2 * npairs; s += 512) {
                const int row = s & 1;
                int p = s >> 1;
                int i = 0;
                for (int a = 0; a < na; a++) {
                    if (p < pcount[a]) { i = act[a]; break; }
                    p -= pcount[a];
                }
                const int colsP = (i + 1) * 32;
                const int c2 = p * 2;
                const int j = rank * colsP + c2;
                const float* P = rp + c_RPB[i] + row * colsP + c2;
                float s0 = 0.f, s1 = 0.f;
                const int ns = c_SR[i];
                for (int sg = 0; sg < ns; sg++) {
                    s0 += P[(sg * 2) * colsP];
                    s1 += P[(sg * 2) * colsP + 1];
                }
                const float* hh = h_s + row * 512;
                const float v0 = sigmoidf_(s0) * hh[j];
                const float v1 = sigmoidf_(s1) * hh[j + 1];
                const int idx = c_OFF[i] + j;
                rh_s[row * 1280 + idx]     = v0;
                rh_s[row * 1280 + idx + 1] = v1;
                const uint32_t off = (uint32_t)(row * 1280 + idx) * 4u;
                st_cluster_b64(peer_rh[0] + off, v0, v1);
                st_cluster_b64(peer_rh[1] + off, v0, v1);
                st_cluster_b64(peer_rh[2] + off, v0, v1);
            }
        }
        CLUSTER_SYNC();

        // ================= pass 3: hn-dots → private partials ===============
        int total3 = 0;
        for (int a = 0; a < na; a++) total3 += c_TH[act[a]];

        for (int task = tid; task < total3; task += 512) {
            int tk = task;
            int i = 0;
            for (int a = 0; a < na; a++) {
                const int ii = act[a];
                if (tk < c_TH[ii]) { i = ii; break; }
                tk -= c_TH[ii];
            }
            const int q = tk & 7; const int seg = tk >> 3; const int c = q * 4;
            const int lc = rank * 32 + c;
            float A0[4] = {0,0,0,0}, A1[4] = {0,0,0,0};
            const float* rh0 = rh_s + c_OFF[i];
            const float* rh1 = rh_s + 1280 + c_OFF[i];
            if (i == 0) {
                dot_s42<16, 32>(ch0_s + seg * 16 * 32 + c,
                                rh0 + seg * 16, rh1 + seg * 16, A0, A1);
            } else if (i == 1) {
                dot_s42<64, 32>(ch1_s + seg * 64 * 32 + c,
                                rh0 + seg * 64, rh1 + seg * 64, A0, A1);
            } else if (i == 2) {
                dot_g42<64>(ch2 + (size_t)(seg * 64) * 128 + lc, 128,
                            rh0 + seg * 64, rh1 + seg * 64, A0, A1);
            } else {
                dot_g42<64>(ch3 + (size_t)(seg * 64) * 128 + lc, 128,
                            rh0 + seg * 64, rh1 + seg * 64, A0, A1);
            }
            if (seg == 0) {
                const int gc = (i << 7) + lc;
                float4 B0 = *(const float4*)&xt[xr0 + gc];
                float4 B1 = *(const float4*)&xt[xr1 + gc];
                A0[0] += B0.x; A0[1] += B0.y; A0[2] += B0.z; A0[3] += B0.w;
                A1[0] += B1.x; A1[1] += B1.y; A1[2] += B1.z; A1[3] += B1.w;
            }
            float* P = hp + c_HPB[i] + (seg * 2) * 32 + c;
            *(float4*)P        = make_float4(A0[0], A0[1], A0[2], A0[3]);
            *(float4*)(P + 32) = make_float4(A1[0], A1[1], A1[2], A1[3]);
        }
        __syncthreads();

        // ================= pass 4: reduce z/hn, gate, update h, exchange ====
        {
            const int npairs = na * 16;
            for (int s = tid; s < 2 * npairs; s += 512) {
                const int row = s & 1;
                const int p = s >> 1;
                const int i = act[p >> 4];
                const int c2 = (p & 15) * 2;
                const int lc = rank * 32 + c2;
                const int gc = (i << 7) + lc;
                const float* Pz = zp + c_ZPB[i] + row * 32 + c2;
                const float* Ph = hp + c_HPB[i] + row * 32 + c2;
                float z0 = 0.f, z1 = 0.f, n0 = 0.f, n1 = 0.f;
                const int nz = c_SZ[i];
                for (int sg = 0; sg < nz; sg++) {
                    z0 += Pz[(sg * 2) * 32];
                    z1 += Pz[(sg * 2) * 32 + 1];
                }
                const int nh = c_SH[i];
                for (int sg = 0; sg < nh; sg++) {
                    n0 += Ph[(sg * 2) * 32];
                    n1 += Ph[(sg * 2) * 32 + 1];
                }
                const float zz0 = sigmoidf_(z0), zz1 = sigmoidf_(z1);
                const float hn0 = sigmoidf_(n0), hn1 = sigmoidf_(n1);
                float* hh = h_s + row * 512;
                const float v0 = zz0 * hn0 + (1.0f - zz0) * hh[gc];
                const float v1 = zz1 * hn1 + (1.0f - zz1) * hh[gc + 1];
                hh[gc] = v0; hh[gc + 1] = v1;
                const uint32_t off = (uint32_t)(row * 512 + gc) * 4u;
                st_cluster_b64(peer_h[0] + off, v0, v1);
                st_cluster_b64(peer_h[1] + off, v0, v1);
                st_cluster_b64(peer_h[2] + off, v0, v1);
            }
        }
        __syncthreads();

        // output: own 128 cols x 2 rows
        if (tid < 256) {
            const int row = tid >> 7;
            const int idx = tid & 127;
            const int i = idx >> 5, c = idx & 31;
            const int gc = i * 128 + rank * 32 + c;
            const size_t xr = row ? xr1 : xr0;
            out[xr + gc] = h_s[row * 512 + gc];
        }
        CLUSTER_SYNC();
    }
}

// ---------------------------------------------------------------------------
extern "C" void kernel_launch(void* const* d_in, const int* in_sizes, int n_in,
                              void* d_out, int out_size) {
    (void)in_sizes; (void)n_in; (void)out_size;
    const float* x  = (const float*)d_in[0];
    const float* W  = (const float*)d_in[1];
    const float* bb = (const float*)d_in[2];
    const float* Wr = (const float*)d_in[3];
    const float* br = (const float*)d_in[4];
    const float* Wz = (const float*)d_in[5];
    const float* bz = (const float*)d_in[6];
    const float* ch[4]; const float* cr[4]; const float* cz[4];
    for (int i = 0; i < 4; i++) {
        ch[i] = (const float*)d_in[7 + 3 * i + 0];
        cr[i] = (const float*)d_in[7 + 3 * i + 1];
        cz[i] = (const float*)d_in[7 + 3 * i + 2];
    }
    float* out = (float*)d_out;

    dim3 grid(GN / BN, GM / BM, 3);
    gemm3_kernel<<<grid, 256>>>(x, W, bb, Wr, br, Wz, bz);

    size_t smem_bytes = 54144 * sizeof(float);   // 216,576 B
    cudaFuncSetAttribute(scan_kernel,
                         cudaFuncAttributeMaxDynamicSharedMemorySize,
                         (int)smem_bytes);
    scan_kernel<<<(NBATCH / 2) * 4, 512, smem_bytes>>>(
        ch[0], cr[0], cz[0],
        ch[1], cr[1], cz[1],
        ch[2], cr[2], cz[2],
        ch[3], cr[3], cz[3],
        out);
}

// round 9
// speedup vs baseline: 1.2836x; 1.2836x over previous
#include <cuda_runtime.h>
#include <cstdint>

// ---------------------------------------------------------------------------
// ClockworkGRU:
//   Phase A: proj[z] = x @ Wz + bz for z in {W, Wr, Wz}   (3x SGEMM, fp32)
//   Phase B: scan — 4-CTA cluster per PAIR of batch elements, column-split.
//   v9: global-weight dots are WARP-coalesced (lanes span consecutive
//       float4 columns of one k-row) -> 4 L1tex wavefronts per warp-load
//       instead of 32. Partial-slot accumulation (no atomics) retained.
// ---------------------------------------------------------------------------

#define GM 32768
#define GK 512
#define GN 512
#define SEQ_LEN 512
#define NBATCH 64

__device__ float g_proj[3ull * GM * GN];

// reduction tables: seg counts per block for r/z/h partials
__constant__ int c_SR[4]  = {8, 4, 6, 8};
__constant__ int c_SZ[4]  = {8, 4, 6, 8};
__constant__ int c_SH[4]  = {8, 4, 6, 8};
__constant__ int c_RPB[4] = {0, 512, 1024, 2176};   // r partial bases
__constant__ int c_ZPB[4] = {0, 512, 768, 1152};    // z partial bases
__constant__ int c_HPB[4] = {0, 512, 768, 1152};    // h partial bases
__constant__ int c_OFF[4] = {0, 128, 384, 768};

// ---------------- helpers ----------------------------------------------------
__device__ __forceinline__ unsigned long long pack2(float x, float y) {
    unsigned long long r;
    asm("mov.b64 %0, {%1, %2};" : "=l"(r) : "f"(x), "f"(y));
    return r;
}
__device__ __forceinline__ void fma2(unsigned long long& d,
                                     unsigned long long a,
                                     unsigned long long b) {
    asm("fma.rn.f32x2 %0, %1, %2, %0;" : "+l"(d) : "l"(a), "l"(b));
}
__device__ __forceinline__ float2 unpack2(unsigned long long v) {
    float2 r;
    asm("mov.b64 {%0, %1}, %2;" : "=f"(r.x), "=f"(r.y) : "l"(v));
    return r;
}
__device__ __forceinline__ float sigmoidf_(float x) {
    return 1.0f / (1.0f + __expf(-x));
}
__device__ __forceinline__ uint32_t smem_u32(const void* p) {
    return (uint32_t)__cvta_generic_to_shared(p);
}
__device__ __forceinline__ uint32_t mapa_u32(uint32_t addr, uint32_t rank) {
    uint32_t r;
    asm("mapa.shared::cluster.u32 %0, %1, %2;" : "=r"(r) : "r"(addr), "r"(rank));
    return r;
}
__device__ __forceinline__ void st_cluster_b64(uint32_t a, float x, float y) {
    unsigned long long v = pack2(x, y);
    asm volatile("st.shared::cluster.b64 [%0], %1;" :: "r"(a), "l"(v) : "memory");
}
#define CLUSTER_SYNC() do {                                           \
    asm volatile("barrier.cluster.arrive.aligned;" ::: "memory");     \
    asm volatile("barrier.cluster.wait.aligned;"   ::: "memory");     \
} while (0)

// ---------------------------------------------------------------------------
// GEMM (unchanged — ~0.95 ms)
// ---------------------------------------------------------------------------
#define BM 128
#define BN 128
#define BKK 8

__global__ void __launch_bounds__(256) gemm3_kernel(
    const float* __restrict__ A,
    const float* __restrict__ W0, const float* __restrict__ b0,
    const float* __restrict__ W1, const float* __restrict__ b1,
    const float* __restrict__ W2, const float* __restrict__ b2)
{
    __shared__ float As[BKK][BM];
    __shared__ float Bs[BKK][BN];

    const int z = blockIdx.z;
    const float* W    = (z == 0) ? W0 : (z == 1 ? W1 : W2);
    const float* bias = (z == 0) ? b0 : (z == 1 ? b1 : b2);
    float* C = g_proj + (size_t)z * GM * GN;

    const int m0 = blockIdx.y * BM;
    const int n0 = blockIdx.x * BN;
    const int tid = threadIdx.x;

    const int a_row = tid >> 1;
    const int a_k   = (tid & 1) * 4;
    const int b_row = tid >> 5;
    const int b_col = (tid & 31) * 4;

    const int warp = tid >> 5;
    const int lane = tid & 31;
    const int row0 = (warp & 3) * 32 + (lane & 3) * 8;
    const int col0 = (warp >> 2) * 64 + (lane >> 2) * 8;

    unsigned long long acc[8][4];
#pragma unroll
    for (int i = 0; i < 8; i++)
#pragma unroll
        for (int j = 0; j < 4; j++) acc[i][j] = 0ull;

    const float* Aptr = A + (size_t)(m0 + a_row) * GK + a_k;
    const float* Wptr = W + (size_t)b_row * GN + n0 + b_col;

    float4 ra = *(const float4*)Aptr;
    float4 rb = *(const float4*)Wptr;

    const int KT = GK / BKK;
    for (int kt = 0; kt < KT; kt++) {
        As[a_k + 0][a_row] = ra.x;
        As[a_k + 1][a_row] = ra.y;
        As[a_k + 2][a_row] = ra.z;
        As[a_k + 3][a_row] = ra.w;
        *(float4*)&Bs[b_row][b_col] = rb;
        __syncthreads();

        if (kt + 1 < KT) {
            ra = *(const float4*)(Aptr + (kt + 1) * BKK);
            rb = *(const float4*)(Wptr + (size_t)(kt + 1) * BKK * GN);
        }

#pragma unroll
        for (int k = 0; k < BKK; k++) {
            float4 a0 = *(const float4*)&As[k][row0];
            float4 a1 = *(const float4*)&As[k][row0 + 4];
            ulonglong2 bq0 = *(const ulonglong2*)&Bs[k][col0];
            ulonglong2 bq1 = *(const ulonglong2*)&Bs[k][col0 + 4];
            unsigned long long av[8];
            av[0] = pack2(a0.x, a0.x); av[1] = pack2(a0.y, a0.y);
            av[2] = pack2(a0.z, a0.z); av[3] = pack2(a0.w, a0.w);
            av[4] = pack2(a1.x, a1.x); av[5] = pack2(a1.y, a1.y);
            av[6] = pack2(a1.z, a1.z); av[7] = pack2(a1.w, a1.w);
#pragma unroll
            for (int i = 0; i < 8; i++) {
                fma2(acc[i][0], av[i], bq0.x);
                fma2(acc[i][1], av[i], bq0.y);
                fma2(acc[i][2], av[i], bq1.x);
                fma2(acc[i][3], av[i], bq1.y);
            }
        }
        __syncthreads();
    }

    float bb[8];
#pragma unroll
    for (int j = 0; j < 8; j++) bb[j] = bias[n0 + col0 + j];

#pragma unroll
    for (int i = 0; i < 8; i++) {
        float o[8];
#pragma unroll
        for (int jp = 0; jp < 4; jp++) {
            float2 v = unpack2(acc[i][jp]);
            o[2 * jp]     = v.x + bb[2 * jp];
            o[2 * jp + 1] = v.y + bb[2 * jp + 1];
        }
        size_t base = (size_t)(m0 + row0 + i) * GN + n0 + col0;
        *(float4*)&C[base]     = make_float4(o[0], o[1], o[2], o[3]);
        *(float4*)&C[base + 4] = make_float4(o[4], o[5], o[6], o[7]);
    }
}

// ---------------------------------------------------------------------------
// warp-coalesced global dots (64 k-rows per task)
// ---------------------------------------------------------------------------

// WIDE lanes each own 4 consecutive cols of every k-row (contiguous 16B/lane).
// Covers 64 rows; all lanes < WIDE active.
template<int WIDE>  // 32 (128 cols) or 24 (96 cols)
__device__ __forceinline__ void wdot_wide(const float* __restrict__ Wp, int stride,
                                          const float* __restrict__ h0,
                                          const float* __restrict__ h1,
                                          float* a0, float* a1, int lane)
{
    const float* p = Wp + lane * 4;
#pragma unroll 8
    for (int k = 0; k < 64; k++) {
        float4 w = *(const float4*)(p + (size_t)k * stride);
        float x0 = h0[k], x1 = h1[k];
        a0[0] = fmaf(x0, w.x, a0[0]); a0[1] = fmaf(x0, w.y, a0[1]);
        a0[2] = fmaf(x0, w.z, a0[2]); a0[3] = fmaf(x0, w.w, a0[3]);
        a1[0] = fmaf(x1, w.x, a1[0]); a1[1] = fmaf(x1, w.y, a1[1]);
        a1[2] = fmaf(x1, w.z, a1[2]); a1[3] = fmaf(x1, w.w, a1[3]);
    }
}

// 32-col matrices (stride 128): 4 rows per warp-load.
// lane -> (subrow = lane>>3, subcol = lane&7). After the loop, a 2-step
// shfl_xor reduces over subrows; lanes 0-7 hold the final column sums.
__device__ __forceinline__ void wdot_w8(const float* __restrict__ Wp,
                                        const float* __restrict__ h0,
                                        const float* __restrict__ h1,
                                        float* a0, float* a1, int lane)
{
    const int sr = lane >> 3, sc = lane & 7;
    const float* p = Wp + sr * 128 + sc * 4;
#pragma unroll 4
    for (int k = 0; k < 64; k += 4) {
        float4 w = *(const float4*)(p + (size_t)k * 128);
        float x0 = h0[k + sr], x1 = h1[k + sr];
        a0[0] = fmaf(x0, w.x, a0[0]); a0[1] = fmaf(x0, w.y, a0[1]);
        a0[2] = fmaf(x0, w.z, a0[2]); a0[3] = fmaf(x0, w.w, a0[3]);
        a1[0] = fmaf(x1, w.x, a1[0]); a1[1] = fmaf(x1, w.y, a1[1]);
        a1[2] = fmaf(x1, w.z, a1[2]); a1[3] = fmaf(x1, w.w, a1[3]);
    }
#pragma unroll
    for (int j = 0; j < 4; j++) {
        a0[j] += __shfl_xor_sync(0xffffffffu, a0[j], 8);
        a0[j] += __shfl_xor_sync(0xffffffffu, a0[j], 16);
        a1[j] += __shfl_xor_sync(0xffffffffu, a1[j], 8);
        a1[j] += __shfl_xor_sync(0xffffffffu, a1[j], 16);
    }
}

// smem dot, KSEG deep, stride STR, 2 rows (thread-level; conflict-free)
template<int KSEG, int STR>
__device__ __forceinline__ void dot_s42(const float* __restrict__ w,
                                        const float* __restrict__ h0,
                                        const float* __restrict__ h1,
                                        float* a0, float* a1)
{
#pragma unroll
    for (int k = 0; k < KSEG; k++) {
        float4 ww = *(const float4*)&w[k * STR];
        float x0 = h0[k], x1 = h1[k];
        a0[0] = fmaf(x0, ww.x, a0[0]); a0[1] = fmaf(x0, ww.y, a0[1]);
        a0[2] = fmaf(x0, ww.z, a0[2]); a0[3] = fmaf(x0, ww.w, a0[3]);
        a1[0] = fmaf(x1, ww.x, a1[0]); a1[1] = fmaf(x1, ww.y, a1[1]);
        a1[2] = fmaf(x1, ww.z, a1[2]); a1[3] = fmaf(x1, ww.w, a1[3]);
    }
}

// ---------------------------------------------------------------------------
__global__ void __launch_bounds__(512, 1) __cluster_dims__(4, 1, 1)
scan_kernel(
    const float* __restrict__ ch0, const float* __restrict__ cr0, const float* __restrict__ cz0,
    const float* __restrict__ ch1, const float* __restrict__ cr1, const float* __restrict__ cz1,
    const float* __restrict__ ch2, const float* __restrict__ cr2, const float* __restrict__ cz2,
    const float* __restrict__ ch3, const float* __restrict__ cr3, const float* __restrict__ cz3,
    float* __restrict__ out)
{
    extern __shared__ float smem[];
    float* h_s   = smem;              // 2 x 512
    float* rh_s  = smem + 1024;       // 2 x 1280
    float* rp    = smem + 3584;       // 4224 r partials
    float* zp    = smem + 7808;       // 1664 z partials
    float* hp    = smem + 9472;       // 1664 hn partials
    float* cr0_s = smem + 11136;      // 128 x 32
    float* cz0_s = smem + 15232;      // 128 x 32
    float* ch0_s = smem + 19328;      // 128 x 32
    float* cr1_s = smem + 23424;      // 256 x 64
    float* cz1_s = smem + 39808;      // 256 x 32
    float* ch1_s = smem + 48000;      // 256 x 32  (end 56192)

    const int rank = blockIdx.x & 3;
    const int bp   = blockIdx.x >> 2;
    const int tid  = threadIdx.x;
    const int wid  = tid >> 5;
    const int lane = tid & 31;

    // ---- preload own-column slices of block-0 and block-1 matrices ---------
    for (int i = tid; i < 1024; i += 512) {
        const int row = i >> 3, c4 = (i & 7) * 4;
        const int src = row * 128 + rank * 32 + c4;
        const int dst = row * 32 + c4;
        *(float4*)&cr0_s[dst] = *(const float4*)&cr0[src];
        *(float4*)&cz0_s[dst] = *(const float4*)&cz0[src];
        *(float4*)&ch0_s[dst] = *(const float4*)&ch0[src];
    }
    for (int i = tid; i < 4096; i += 512) {
        const int row = i >> 4, c4 = (i & 15) * 4;
        *(float4*)&cr1_s[row * 64 + c4] =
            *(const float4*)&cr1[row * 256 + rank * 64 + c4];
    }
    for (int i = tid; i < 2048; i += 512) {
        const int row = i >> 3, c4 = (i & 7) * 4;
        *(float4*)&cz1_s[row * 32 + c4] =
            *(const float4*)&cz1[row * 128 + rank * 32 + c4];
        *(float4*)&ch1_s[row * 32 + c4] =
            *(const float4*)&ch1[row * 128 + rank * 32 + c4];
    }
    h_s[tid] = 0.0f; h_s[512 + tid] = 0.0f;
    __syncthreads();
    CLUSTER_SYNC();

    uint32_t peer_rh[3], peer_h[3];
    {
        int p = 0;
        for (int r = 0; r < 4; r++) {
            if (r == rank) continue;
            peer_rh[p] = mapa_u32(smem_u32(rh_s), (uint32_t)r);
            peer_h[p]  = mapa_u32(smem_u32(h_s),  (uint32_t)r);
            p++;
        }
    }

    const float* xt  = g_proj;
    const float* xrt = g_proj + (size_t)GM * GN;
    const float* xzt = g_proj + 2ull * GM * GN;

    for (int t = 0; t < SEQ_LEN; t++) {
        const bool aa1 = (t & 1) == 0, aa2 = (t & 3) == 0, aa3 = (t & 7) == 0;
        int act[4]; int na = 0;
        act[na++] = 0;
        if (aa1) act[na++] = 1;
        if (aa2) act[na++] = 2;
        if (aa3) act[na++] = 3;

        const size_t xr0 = ((size_t)(bp * 2 + 0) * SEQ_LEN + t) * GN;
        const size_t xr1 = ((size_t)(bp * 2 + 1) * SEQ_LEN + t) * GN;

        // ============ pass 1: r/z dots → private partial slots ==============
        // (a) warp tasks first: global blocks 2,3 (coalesced, long latency)
        {
            const int nwt = (aa2 ? 12 : 0) + (aa3 ? 16 : 0);
            for (int wt = wid; wt < nwt; wt += 16) {
                int k = wt;
                float A0[4] = {0,0,0,0}, A1[4] = {0,0,0,0};
                if (aa2 && k < 6) {                       // block2 r (96 cols)
                    const int seg = k;
                    if (lane < 24) {
                        wdot_wide<24>(cr2 + (size_t)(seg * 64) * 384 + rank * 96,
                                      384, h_s + seg * 64, h_s + 512 + seg * 64,
                                      A0, A1, lane);
                        if (seg == 0) {
                            const int j = rank * 96 + lane * 4;
                            float4 B0 = *(const float4*)&xrt[xr0 + j];
                            float4 B1 = *(const float4*)&xrt[xr1 + j];
                            A0[0]+=B0.x; A0[1]+=B0.y; A0[2]+=B0.z; A0[3]+=B0.w;
                            A1[0]+=B1.x; A1[1]+=B1.y; A1[2]+=B1.z; A1[3]+=B1.w;
                        }
                        float* P = rp + c_RPB[2] + (seg * 2) * 96 + lane * 4;
                        *(float4*)P        = make_float4(A0[0],A0[1],A0[2],A0[3]);
                        *(float4*)(P + 96) = make_float4(A1[0],A1[1],A1[2],A1[3]);
                    }
                    continue;
                }
                if (aa2) { k -= 6;
                if (k < 6) {                              // block2 z (32 cols)
                    const int seg = k;
                    wdot_w8(cz2 + (size_t)(seg * 64) * 128 + rank * 32,
                            h_s + seg * 64, h_s + 512 + seg * 64, A0, A1, lane);
                    if (lane < 8) {
                        if (seg == 0) {
                            const int gc = 256 + rank * 32 + lane * 4;
                            float4 B0 = *(const float4*)&xzt[xr0 + gc];
                            float4 B1 = *(const float4*)&xzt[xr1 + gc];
                            A0[0]+=B0.x; A0[1]+=B0.y; A0[2]+=B0.z; A0[3]+=B0.w;
                            A1[0]+=B1.x; A1[1]+=B1.y; A1[2]+=B1.z; A1[3]+=B1.w;
                        }
                        float* P = zp + c_ZPB[2] + (seg * 2) * 32 + lane * 4;
                        *(float4*)P        = make_float4(A0[0],A0[1],A0[2],A0[3]);
                        *(float4*)(P + 32) = make_float4(A1[0],A1[1],A1[2],A1[3]);
                    }
                    continue;
                }
                k -= 6; }
                if (k < 8) {                              // block3 r (128 cols)
                    const int seg = k;
                    wdot_wide<32>(cr3 + (size_t)(seg * 64) * 512 + rank * 128,
                                  512, h_s + seg * 64, h_s + 512 + seg * 64,
                                  A0, A1, lane);
                    if (seg == 0) {
                        const int j = rank * 128 + lane * 4;
                        float4 B0 = *(const float4*)&xrt[xr0 + j];
                        float4 B1 = *(const float4*)&xrt[xr1 + j];
                        A0[0]+=B0.x; A0[1]+=B0.y; A0[2]+=B0.z; A0[3]+=B0.w;
                        A1[0]+=B1.x; A1[1]+=B1.y; A1[2]+=B1.z; A1[3]+=B1.w;
                    }
                    float* P = rp + c_RPB[3] + (seg * 2) * 128 + lane * 4;
                    *(float4*)P         = make_float4(A0[0],A0[1],A0[2],A0[3]);
                    *(float4*)(P + 128) = make_float4(A1[0],A1[1],A1[2],A1[3]);
                } else {                                  // block3 z (32 cols)
                    const int seg = k - 8;
                    wdot_w8(cz3 + (size_t)(seg * 64) * 128 + rank * 32,
                            h_s + seg * 64, h_s + 512 + seg * 64, A0, A1, lane);
                    if (lane < 8) {
                        if (seg == 0) {
                            const int gc = 384 + rank * 32 + lane * 4;
                            float4 B0 = *(const float4*)&xzt[xr0 + gc];
                            float4 B1 = *(const float4*)&xzt[xr1 + gc];
                            A0[0]+=B0.x; A0[1]+=B0.y; A0[2]+=B0.z; A0[3]+=B0.w;
                            A1[0]+=B1.x; A1[1]+=B1.y; A1[2]+=B1.z; A1[3]+=B1.w;
                        }
                        float* P = zp + c_ZPB[3] + (seg * 2) * 32 + lane * 4;
                        *(float4*)P        = make_float4(A0[0],A0[1],A0[2],A0[3]);
                        *(float4*)(P + 32) = make_float4(A1[0],A1[1],A1[2],A1[3]);
                    }
                }
            }
        }
        // (b) thread tasks: SMEM blocks 0,1
        {
            const int totalT = 128 + (aa1 ? 96 : 0);
            for (int task = tid; task < totalT; task += 512) {
                int tk = task;
                float A0[4] = {0,0,0,0}, A1[4] = {0,0,0,0};
                if (tk < 64) {                       // b0 r
                    const int q = tk & 7, seg = tk >> 3, c = q * 4;
                    dot_s42<16, 32>(cr0_s + seg * 16 * 32 + c,
                                    h_s + seg * 16, h_s + 512 + seg * 16, A0, A1);
                    if (seg == 0) {
                        const int j = rank * 32 + c;
                        float4 B0 = *(const float4*)&xrt[xr0 + j];
                        float4 B1 = *(const float4*)&xrt[xr1 + j];
                        A0[0]+=B0.x; A0[1]+=B0.y; A0[2]+=B0.z; A0[3]+=B0.w;
                        A1[0]+=B1.x; A1[1]+=B1.y; A1[2]+=B1.z; A1[3]+=B1.w;
                    }
                    float* P = rp + (seg * 2) * 32 + c;
                    *(float4*)P        = make_float4(A0[0],A0[1],A0[2],A0[3]);
                    *(float4*)(P + 32) = make_float4(A1[0],A1[1],A1[2],A1[3]);
                } else if ((tk -= 64) < 64) {        // b0 z
                    const int q = tk & 7, seg = tk >> 3, c = q * 4;
                    dot_s42<16, 32>(cz0_s + seg * 16 * 32 + c,
                                    h_s + seg * 16, h_s + 512 + seg * 16, A0, A1);
                    if (seg == 0) {
                        const int gc = rank * 32 + c;
                        float4 B0 = *(const float4*)&xzt[xr0 + gc];
                        float4 B1 = *(const float4*)&xzt[xr1 + gc];
                        A0[0]+=B0.x; A0[1]+=B0.y; A0[2]+=B0.z; A0[3]+=B0.w;
                        A1[0]+=B1.x; A1[1]+=B1.y; A1[2]+=B1.z; A1[3]+=B1.w;
                    }
                    float* P = zp + (seg * 2) * 32 + c;
                    *(float4*)P        = make_float4(A0[0],A0[1],A0[2],A0[3]);
                    *(float4*)(P + 32) = make_float4(A1[0],A1[1],A1[2],A1[3]);
                } else if ((tk -= 64) < 64) {        // b1 r
                    const int q = tk & 15, seg = tk >> 4, c = q * 4;
                    dot_s42<64, 64>(cr1_s + seg * 64 * 64 + c,
                                    h_s + seg * 64, h_s + 512 + seg * 64, A0, A1);
                    if (seg == 0) {
                        const int j = rank * 64 + c;
                        float4 B0 = *(const float4*)&xrt[xr0 + j];
                        float4 B1 = *(const float4*)&xrt[xr1 + j];
                        A0[0]+=B0.x; A0[1]+=B0.y; A0[2]+=B0.z; A0[3]+=B0.w;
                        A1[0]+=B1.x; A1[1]+=B1.y; A1[2]+=B1.z; A1[3]+=B1.w;
                    }
                    float* P = rp + c_RPB[1] + (seg * 2) * 64 + c;
                    *(float4*)P        = make_float4(A0[0],A0[1],A0[2],A0[3]);
                    *(float4*)(P + 64) = make_float4(A1[0],A1[1],A1[2],A1[3]);
                } else {                             // b1 z
                    tk -= 64;
                    const int q = tk & 7, seg = tk >> 3, c = q * 4;
                    dot_s42<64, 32>(cz1_s + seg * 64 * 32 + c,
                                    h_s + seg * 64, h_s + 512 + seg * 64, A0, A1);
                    if (seg == 0) {
                        const int gc = 128 + rank * 32 + c;
                        float4 B0 = *(const float4*)&xzt[xr0 + gc];
                        float4 B1 = *(const float4*)&xzt[xr1 + gc];
                        A0[0]+=B0.x; A0[1]+=B0.y; A0[2]+=B0.z; A0[3]+=B0.w;
                        A1[0]+=B1.x; A1[1]+=B1.y; A1[2]+=B1.z; A1[3]+=B1.w;
                    }
                    float* P = zp + c_ZPB[1] + (seg * 2) * 32 + c;
                    *(float4*)P        = make_float4(A0[0],A0[1],A0[2],A0[3]);
                    *(float4*)(P + 32) = make_float4(A1[0],A1[1],A1[2],A1[3]);
                }
            }
        }
        __syncthreads();

        // ============ pass 2: reduce r, rh = sig(r)*h, exchange =============
        {
            int pcount[4]; int npairs = 0;
            for (int a = 0; a < na; a++) {
                pcount[a] = (act[a] + 1) * 16;
                npairs += pcount[a];
            }
            for (int s = tid; s < 2 * npairs; s += 512) {
                const int row = s & 1;
                int p = s >> 1;
                int i = 0;
                for (int a = 0; a < na; a++) {
                    if (p < pcount[a]) { i = act[a]; break; }
                    p -= pcount[a];
                }
                const int colsP = (i + 1) * 32;
                const int c2 = p * 2;
                const int j = rank * colsP + c2;
                const float* P = rp + c_RPB[i] + row * colsP + c2;
                float s0 = 0.f, s1 = 0.f;
                const int ns = c_SR[i];
                for (int sg = 0; sg < ns; sg++) {
                    s0 += P[(sg * 2) * colsP];
                    s1 += P[(sg * 2) * colsP + 1];
                }
                const float* hh = h_s + row * 512;
                const float v0 = sigmoidf_(s0) * hh[j];
                const float v1 = sigmoidf_(s1) * hh[j + 1];
                const int idx = c_OFF[i] + j;
                rh_s[row * 1280 + idx]     = v0;
                rh_s[row * 1280 + idx + 1] = v1;
                const uint32_t off = (uint32_t)(row * 1280 + idx) * 4u;
                st_cluster_b64(peer_rh[0] + off, v0, v1);
                st_cluster_b64(peer_rh[1] + off, v0, v1);
                st_cluster_b64(peer_rh[2] + off, v0, v1);
            }
        }
        CLUSTER_SYNC();

        // ============ pass 3: hn-dots → private partials =====================
        // (a) warp tasks: blocks 2,3 (coalesced w8 over rh)
        {
            const int nwh = (aa2 ? 6 : 0) + (aa3 ? 8 : 0);
            for (int wt = wid; wt < nwh; wt += 16) {
                int k = wt;
                float A0[4] = {0,0,0,0}, A1[4] = {0,0,0,0};
                int i, seg;
                const float* base;
                if (aa2 && k < 6) { i = 2; seg = k; base = ch2; }
                else { if (aa2) k -= 6; i = 3; seg = k; base = ch3; }
                wdot_w8(base + (size_t)(seg * 64) * 128 + rank * 32,
                        rh_s + c_OFF[i] + seg * 64,
                        rh_s + 1280 + c_OFF[i] + seg * 64, A0, A1, lane);
                if (lane < 8) {
                    if (seg == 0) {
                        const int gc = (i << 7) + rank * 32 + lane * 4;
                        float4 B0 = *(const float4*)&xt[xr0 + gc];
                        float4 B1 = *(const float4*)&xt[xr1 + gc];
                        A0[0]+=B0.x; A0[1]+=B0.y; A0[2]+=B0.z; A0[3]+=B0.w;
                        A1[0]+=B1.x; A1[1]+=B1.y; A1[2]+=B1.z; A1[3]+=B1.w;
                    }
                    float* P = hp + c_HPB[i] + (seg * 2) * 32 + lane * 4;
                    *(float4*)P        = make_float4(A0[0],A0[1],A0[2],A0[3]);
                    *(float4*)(P + 32) = make_float4(A1[0],A1[1],A1[2],A1[3]);
                }
            }
        }
        // (b) thread tasks: SMEM blocks 0,1
        {
            const int totalTh = 64 + (aa1 ? 32 : 0);
            for (int task = tid; task < totalTh; task += 512) {
                int tk = task;
                float A0[4] = {0,0,0,0}, A1[4] = {0,0,0,0};
                if (tk < 64) {                       // b0 h
                    const int q = tk & 7, seg = tk >> 3, c = q * 4;
                    dot_s42<16, 32>(ch0_s + seg * 16 * 32 + c,
                                    rh_s + seg * 16, rh_s + 1280 + seg * 16,
                                    A0, A1);
                    if (seg == 0) {
                        const int gc = rank * 32 + c;
                        float4 B0 = *(const float4*)&xt[xr0 + gc];
                        float4 B1 = *(const float4*)&xt[xr1 + gc];
                        A0[0]+=B0.x; A0[1]+=B0.y; A0[2]+=B0.z; A0[3]+=B0.w;
                        A1[0]+=B1.x; A1[1]+=B1.y; A1[2]+=B1.z; A1[3]+=B1.w;
                    }
                    float* P = hp + (seg * 2) * 32 + c;
                    *(float4*)P        = make_float4(A0[0],A0[1],A0[2],A0[3]);
                    *(float4*)(P + 32) = make_float4(A1[0],A1[1],A1[2],A1[3]);
                } else {                             // b1 h
                    tk -= 64;
                    const int q = tk & 7, seg = tk >> 3, c = q * 4;
                    dot_s42<64, 32>(ch1_s + seg * 64 * 32 + c,
                                    rh_s + 128 + seg * 64,
                                    rh_s + 1280 + 128 + seg * 64, A0, A1);
                    if (seg == 0) {
                        const int gc = 128 + rank * 32 + c;
                        float4 B0 = *(const float4*)&xt[xr0 + gc];
                        float4 B1 = *(const float4*)&xt[xr1 + gc];
                        A0[0]+=B0.x; A0[1]+=B0.y; A0[2]+=B0.z; A0[3]+=B0.w;
                        A1[0]+=B1.x; A1[1]+=B1.y; A1[2]+=B1.z; A1[3]+=B1.w;
                    }
                    float* P = hp + c_HPB[1] + (seg * 2) * 32 + c;
                    *(float4*)P        = make_float4(A0[0],A0[1],A0[2],A0[3]);
                    *(float4*)(P + 32) = make_float4(A1[0],A1[1],A1[2],A1[3]);
                }
            }
        }
        __syncthreads();

        // ============ pass 4: reduce z/hn, gate, update h, exchange ==========
        {
            const int npairs = na * 16;
            for (int s = tid; s < 2 * npairs; s += 512) {
                const int row = s & 1;
                const int p = s >> 1;
                const int i = act[p >> 4];
                const int c2 = (p & 15) * 2;
                const int lc = rank * 32 + c2;
                const int gc = (i << 7) + lc;
                const float* Pz = zp + c_ZPB[i] + row * 32 + c2;
                const float* Ph = hp + c_HPB[i] + row * 32 + c2;
                float z0 = 0.f, z1 = 0.f, n0 = 0.f, n1 = 0.f;
                const int nz = c_SZ[i];
                for (int sg = 0; sg < nz; sg++) {
                    z0 += Pz[(sg * 2) * 32];
                    z1 += Pz[(sg * 2) * 32 + 1];
                }
                const int nh = c_SH[i];
                for (int sg = 0; sg < nh; sg++) {
                    n0 += Ph[(sg * 2) * 32];
                    n1 += Ph[(sg * 2) * 32 + 1];
                }
                const float zz0 = sigmoidf_(z0), zz1 = sigmoidf_(z1);
                const float hn0 = sigmoidf_(n0), hn1 = sigmoidf_(n1);
                float* hh = h_s + row * 512;
                const float v0 = zz0 * hn0 + (1.0f - zz0) * hh[gc];
                const float v1 = zz1 * hn1 + (1.0f - zz1) * hh[gc + 1];
                hh[gc] = v0; hh[gc + 1] = v1;
                const uint32_t off = (uint32_t)(row * 512 + gc) * 4u;
                st_cluster_b64(peer_h[0] + off, v0, v1);
                st_cluster_b64(peer_h[1] + off, v0, v1);
                st_cluster_b64(peer_h[2] + off, v0, v1);
            }
        }
        __syncthreads();

        // output: own 128 cols x 2 rows
        if (tid < 256) {
            const int row = tid >> 7;
            const int idx = tid & 127;
            const int i = idx >> 5, c = idx & 31;
            const int gc = i * 128 + rank * 32 + c;
            const size_t xr = row ? xr1 : xr0;
            out[xr + gc] = h_s[row * 512 + gc];
        }
        CLUSTER_SYNC();
    }
}

// ---------------------------------------------------------------------------
extern "C" void kernel_launch(void* const* d_in, const int* in_sizes, int n_in,
                              void* d_out, int out_size) {
    (void)in_sizes; (void)n_in; (void)out_size;
    const float* x  = (const float*)d_in[0];
    const float* W  = (const float*)d_in[1];
    const float* bb = (const float*)d_in[2];
    const float* Wr = (const float*)d_in[3];
    const float* br = (const float*)d_in[4];
    const float* Wz = (const float*)d_in[5];
    const float* bz = (const float*)d_in[6];
    const float* ch[4]; const float* cr[4]; const float* cz[4];
    for (int i = 0; i < 4; i++) {
        ch[i] = (const float*)d_in[7 + 3 * i + 0];
        cr[i] = (const float*)d_in[7 + 3 * i + 1];
        cz[i] = (const float*)d_in[7 + 3 * i + 2];
    }
    float* out = (float*)d_out;

    dim3 grid(GN / BN, GM / BM, 3);
    gemm3_kernel<<<grid, 256>>>(x, W, bb, Wr, br, Wz, bz);

    size_t smem_bytes = 56192 * sizeof(float);   // 224,768 B
    cudaFuncSetAttribute(scan_kernel,
                         cudaFuncAttributeMaxDynamicSharedMemorySize,
                         (int)smem_bytes);
    scan_kernel<<<(NBATCH / 2) * 4, 512, smem_bytes>>>(
        ch[0], cr[0], cz[0],
        ch[1], cr[1], cz[1],
        ch[2], cr[2], cz[2],
        ch[3], cr[3], cz[3],
        out);
}

// round 10
// speedup vs baseline: 1.4752x; 1.1492x over previous
#include <cuda_runtime.h>
#include <cstdint>

// ---------------------------------------------------------------------------
// ClockworkGRU:
//   Phase A: clockwork-sparse projections — proj cols for block i are only
//            computed at timesteps t % 2^i == 0 (47% of the dense GEMM).
//   Phase B: scan — 4-CTA cluster per PAIR of batch elements, column-split,
//            warp-coalesced global dots with deep explicit prefetch.
// ---------------------------------------------------------------------------

#define GM 32768
#define GK 512
#define GN 512
#define SEQ_LEN 512
#define NBATCH 64

__device__ float g_proj[3ull * GM * GN];

__constant__ int c_SR[4]  = {8, 4, 6, 8};
__constant__ int c_SZ[4]  = {8, 4, 6, 8};
__constant__ int c_SH[4]  = {8, 4, 6, 8};
__constant__ int c_RPB[4] = {0, 512, 1024, 2176};
__constant__ int c_ZPB[4] = {0, 512, 768, 1152};
__constant__ int c_HPB[4] = {0, 512, 768, 1152};
__constant__ int c_OFF[4] = {0, 128, 384, 768};

// ---------------- helpers ----------------------------------------------------
__device__ __forceinline__ unsigned long long pack2(float x, float y) {
    unsigned long long r;
    asm("mov.b64 %0, {%1, %2};" : "=l"(r) : "f"(x), "f"(y));
    return r;
}
__device__ __forceinline__ void fma2(unsigned long long& d,
                                     unsigned long long a,
                                     unsigned long long b) {
    asm("fma.rn.f32x2 %0, %1, %2, %0;" : "+l"(d) : "l"(a), "l"(b));
}
__device__ __forceinline__ float2 unpack2(unsigned long long v) {
    float2 r;
    asm("mov.b64 {%0, %1}, %2;" : "=f"(r.x), "=f"(r.y) : "l"(v));
    return r;
}
__device__ __forceinline__ float sigmoidf_(float x) {
    return 1.0f / (1.0f + __expf(-x));
}
__device__ __forceinline__ uint32_t smem_u32(const void* p) {
    return (uint32_t)__cvta_generic_to_shared(p);
}
__device__ __forceinline__ uint32_t mapa_u32(uint32_t addr, uint32_t rank) {
    uint32_t r;
    asm("mapa.shared::cluster.u32 %0, %1, %2;" : "=r"(r) : "r"(addr), "r"(rank));
    return r;
}
__device__ __forceinline__ void st_cluster_b64(uint32_t a, float x, float y) {
    unsigned long long v = pack2(x, y);
    asm volatile("st.shared::cluster.b64 [%0], %1;" :: "r"(a), "l"(v) : "memory");
}
#define CLUSTER_SYNC() do {                                           \
    asm volatile("barrier.cluster.arrive.aligned;" ::: "memory");     \
    asm volatile("barrier.cluster.wait.aligned;"   ::: "memory");     \
} while (0)

// ---------------------------------------------------------------------------
// Clockwork-sparse GEMM: blockIdx.z = z*4 + colblock i. Rows restricted to
// timesteps active for block i (t % 2^i == 0); 47% of the dense FLOPs.
// ---------------------------------------------------------------------------
#define BM 128
#define BN 128
#define BKK 8

__global__ void __launch_bounds__(256) gemm3_kernel(
    const float* __restrict__ A,
    const float* __restrict__ W0, const float* __restrict__ b0,
    const float* __restrict__ W1, const float* __restrict__ b1,
    const float* __restrict__ W2, const float* __restrict__ b2)
{
    __shared__ float As[BKK][BM];
    __shared__ float Bs[BKK][BN];

    const int zi = blockIdx.z;
    const int z  = zi >> 2;        // 0..2 (xt, xrt, xzt source weight)
    const int cb = zi & 3;         // col block 0..3, period 2^cb
    const int rpb_log = 9 - cb;    // log2(rows per batch) = log2(512 >> cb)
    const int ntiles = (NBATCH << rpb_log) >> 7;   // (64 * 512>>cb) / 128
    if ((int)blockIdx.y >= ntiles) return;

    const float* W    = (z == 0) ? W0 : (z == 1 ? W1 : W2);
    const float* bias = (z == 0) ? b0 : (z == 1 ? b1 : b2);
    float* C = g_proj + (size_t)z * GM * GN;

    const int m0 = blockIdx.y * BM;      // packed active-row tile base
    const int n0 = cb * 128;             // column offset
    const int tid = threadIdx.x;

    const int a_row = tid >> 1;
    const int a_k   = (tid & 1) * 4;
    const int b_row = tid >> 5;
    const int b_col = (tid & 31) * 4;

    const int warp = tid >> 5;
    const int lane = tid & 31;
    const int row0 = (warp & 3) * 32 + (lane & 3) * 8;
    const int col0 = (warp >> 2) * 64 + (lane >> 2) * 8;

    // packed row -> actual row:  b = g >> rpb_log; t = (g & (rpb-1)) << cb
    const int rpb_mask = (1 << rpb_log) - 1;
    const int gA = m0 + a_row;
    const int arow_act = ((gA >> rpb_log) << 9) + ((gA & rpb_mask) << cb);

    unsigned long long acc[8][4];
#pragma unroll
    for (int i = 0; i < 8; i++)
#pragma unroll
        for (int j = 0; j < 4; j++) acc[i][j] = 0ull;

    const float* Aptr = A + (size_t)arow_act * GK + a_k;
    const float* Wptr = W + (size_t)b_row * GN + n0 + b_col;

    float4 ra = *(const float4*)Aptr;
    float4 rb = *(const float4*)Wptr;

    const int KT = GK / BKK;
    for (int kt = 0; kt < KT; kt++) {
        As[a_k + 0][a_row] = ra.x;
        As[a_k + 1][a_row] = ra.y;
        As[a_k + 2][a_row] = ra.z;
        As[a_k + 3][a_row] = ra.w;
        *(float4*)&Bs[b_row][b_col] = rb;
        __syncthreads();

        if (kt + 1 < KT) {
            ra = *(const float4*)(Aptr + (kt + 1) * BKK);
            rb = *(const float4*)(Wptr + (size_t)(kt + 1) * BKK * GN);
        }

#pragma unroll
        for (int k = 0; k < BKK; k++) {
            float4 a0 = *(const float4*)&As[k][row0];
            float4 a1 = *(const float4*)&As[k][row0 + 4];
            ulonglong2 bq0 = *(const ulonglong2*)&Bs[k][col0];
            ulonglong2 bq1 = *(const ulonglong2*)&Bs[k][col0 + 4];
            unsigned long long av[8];
            av[0] = pack2(a0.x, a0.x); av[1] = pack2(a0.y, a0.y);
            av[2] = pack2(a0.z, a0.z); av[3] = pack2(a0.w, a0.w);
            av[4] = pack2(a1.x, a1.x); av[5] = pack2(a1.y, a1.y);
            av[6] = pack2(a1.z, a1.z); av[7] = pack2(a1.w, a1.w);
#pragma unroll
            for (int i = 0; i < 8; i++) {
                fma2(acc[i][0], av[i], bq0.x);
                fma2(acc[i][1], av[i], bq0.y);
                fma2(acc[i][2], av[i], bq1.x);
                fma2(acc[i][3], av[i], bq1.y);
            }
        }
        __syncthreads();
    }

    float bb[8];
#pragma unroll
    for (int j = 0; j < 8; j++) bb[j] = bias[n0 + col0 + j];

#pragma unroll
    for (int i = 0; i < 8; i++) {
        float o[8];
#pragma unroll
        for (int jp = 0; jp < 4; jp++) {
            float2 v = unpack2(acc[i][jp]);
            o[2 * jp]     = v.x + bb[2 * jp];
            o[2 * jp + 1] = v.y + bb[2 * jp + 1];
        }
        const int g2 = m0 + row0 + i;
        const int crow = ((g2 >> rpb_log) << 9) + ((g2 & rpb_mask) << cb);
        size_t base = (size_t)crow * GN + n0 + col0;
        *(float4*)&C[base]     = make_float4(o[0], o[1], o[2], o[3]);
        *(float4*)&C[base + 4] = make_float4(o[4], o[5], o[6], o[7]);
    }
}

// ---------------------------------------------------------------------------
// warp-coalesced global dots, deep explicit prefetch
// ---------------------------------------------------------------------------

// WIDE lanes each own 4 consecutive cols of every k-row; 64 rows,
// 8+8 double-buffered.
template<int WIDE>  // 32 (128 cols) or 24 (96 cols)
__device__ __forceinline__ void wdot_wide(const float* __restrict__ Wp, int stride,
                                          const float* __restrict__ h0,
                                          const float* __restrict__ h1,
                                          float* a0, float* a1, int lane)
{
    const float* p = Wp + lane * 4;
    float4 A[8], B[8];
#pragma unroll
    for (int r = 0; r < 8; r++) A[r] = *(const float4*)(p + (size_t)r * stride);
#pragma unroll
    for (int kb = 0; kb < 64; kb += 16) {
#pragma unroll
        for (int r = 0; r < 8; r++)
            B[r] = *(const float4*)(p + (size_t)(kb + 8 + r) * stride);
#pragma unroll
        for (int r = 0; r < 8; r++) {
            float x0 = h0[kb + r], x1 = h1[kb + r];
            a0[0] = fmaf(x0, A[r].x, a0[0]); a0[1] = fmaf(x0, A[r].y, a0[1]);
            a0[2] = fmaf(x0, A[r].z, a0[2]); a0[3] = fmaf(x0, A[r].w, a0[3]);
            a1[0] = fmaf(x1, A[r].x, a1[0]); a1[1] = fmaf(x1, A[r].y, a1[1]);
            a1[2] = fmaf(x1, A[r].z, a1[2]); a1[3] = fmaf(x1, A[r].w, a1[3]);
        }
        if (kb + 16 < 64) {
#pragma unroll
            for (int r = 0; r < 8; r++)
                A[r] = *(const float4*)(p + (size_t)(kb + 16 + r) * stride);
        }
#pragma unroll
        for (int r = 0; r < 8; r++) {
            float x0 = h0[kb + 8 + r], x1 = h1[kb + 8 + r];
            a0[0] = fmaf(x0, B[r].x, a0[0]); a0[1] = fmaf(x0, B[r].y, a0[1]);
            a0[2] = fmaf(x0, B[r].z, a0[2]); a0[3] = fmaf(x0, B[r].w, a0[3]);
            a1[0] = fmaf(x1, B[r].x, a1[0]); a1[1] = fmaf(x1, B[r].y, a1[1]);
            a1[2] = fmaf(x1, B[r].z, a1[2]); a1[3] = fmaf(x1, B[r].w, a1[3]);
        }
    }
}

// 32-col matrices (stride 128): 4 rows per warp-load; all 16 loads
// prefetched into two 8-buffers before consumption. 2-step shfl reduce;
// lanes 0-7 hold final column sums.
__device__ __forceinline__ void wdot_w8(const float* __restrict__ Wp,
                                        const float* __restrict__ h0,
                                        const float* __restrict__ h1,
                                        float* a0, float* a1, int lane)
{
    const int sr = lane >> 3, sc = lane & 7;
    const float* p = Wp + sr * 128 + sc * 4;
    float4 A[8], B[8];
#pragma unroll
    for (int i = 0; i < 8; i++)
        A[i] = *(const float4*)(p + (size_t)(i * 4) * 128);
#pragma unroll
    for (int i = 0; i < 8; i++)
        B[i] = *(const float4*)(p + (size_t)((i + 8) * 4) * 128);
#pragma unroll
    for (int i = 0; i < 8; i++) {
        const int k = i * 4;
        float x0 = h0[k + sr], x1 = h1[k + sr];
        a0[0] = fmaf(x0, A[i].x, a0[0]); a0[1] = fmaf(x0, A[i].y, a0[1]);
        a0[2] = fmaf(x0, A[i].z, a0[2]); a0[3] = fmaf(x0, A[i].w, a0[3]);
        a1[0] = fmaf(x1, A[i].x, a1[0]); a1[1] = fmaf(x1, A[i].y, a1[1]);
        a1[2] = fmaf(x1, A[i].z, a1[2]); a1[3] = fmaf(x1, A[i].w, a1[3]);
    }
#pragma unroll
    for (int i = 0; i < 8; i++) {
        const int k = (i + 8) * 4;
        float x0 = h0[k + sr], x1 = h1[k + sr];
        a0[0] = fmaf(x0, B[i].x, a0[0]); a0[1] = fmaf(x0, B[i].y, a0[1]);
        a0[2] = fmaf(x0, B[i].z, a0[2]); a0[3] = fmaf(x0, B[i].w, a0[3]);
        a1[0] = fmaf(x1, B[i].x, a1[0]); a1[1] = fmaf(x1, B[i].y, a1[1]);
        a1[2] = fmaf(x1, B[i].z, a1[2]); a1[3] = fmaf(x1, B[i].w, a1[3]);
    }
#pragma unroll
    for (int j = 0; j < 4; j++) {
        a0[j] += __shfl_xor_sync(0xffffffffu, a0[j], 8);
        a0[j] += __shfl_xor_sync(0xffffffffu, a0[j], 16);
        a1[j] += __shfl_xor_sync(0xffffffffu, a1[j], 8);
        a1[j] += __shfl_xor_sync(0xffffffffu, a1[j], 16);
    }
}

// smem dot, KSEG deep, stride STR, 2 rows
template<int KSEG, int STR>
__device__ __forceinline__ void dot_s42(const float* __restrict__ w,
                                        const float* __restrict__ h0,
                                        const float* __restrict__ h1,
                                        float* a0, float* a1)
{
#pragma unroll
    for (int k = 0; k < KSEG; k++) {
        float4 ww = *(const float4*)&w[k * STR];
        float x0 = h0[k], x1 = h1[k];
        a0[0] = fmaf(x0, ww.x, a0[0]); a0[1] = fmaf(x0, ww.y, a0[1]);
        a0[2] = fmaf(x0, ww.z, a0[2]); a0[3] = fmaf(x0, ww.w, a0[3]);
        a1[0] = fmaf(x1, ww.x, a1[0]); a1[1] = fmaf(x1, ww.y, a1[1]);
        a1[2] = fmaf(x1, ww.z, a1[2]); a1[3] = fmaf(x1, ww.w, a1[3]);
    }
}

// ---------------------------------------------------------------------------
__global__ void __launch_bounds__(512, 1) __cluster_dims__(4, 1, 1)
scan_kernel(
    const float* __restrict__ ch0, const float* __restrict__ cr0, const float* __restrict__ cz0,
    const float* __restrict__ ch1, const float* __restrict__ cr1, const float* __restrict__ cz1,
    const float* __restrict__ ch2, const float* __restrict__ cr2, const float* __restrict__ cz2,
    const float* __restrict__ ch3, const float* __restrict__ cr3, const float* __restrict__ cz3,
    float* __restrict__ out)
{
    extern __shared__ float smem[];
    float* h_s   = smem;              // 2 x 512
    float* rh_s  = smem + 1024;       // 2 x 1280
    float* rp    = smem + 3584;       // 4224 r partials
    float* zp    = smem + 7808;       // 1664 z partials
    float* hp    = smem + 9472;       // 1664 hn partials
    float* cr0_s = smem + 11136;      // 128 x 32
    float* cz0_s = smem + 15232;      // 128 x 32
    float* ch0_s = smem + 19328;      // 128 x 32
    float* cr1_s = smem + 23424;      // 256 x 64
    float* cz1_s = smem + 39808;      // 256 x 32
    float* ch1_s = smem + 48000;      // 256 x 32  (end 56192)

    const int rank = blockIdx.x & 3;
    const int bp   = blockIdx.x >> 2;
    const int tid  = threadIdx.x;
    const int wid  = tid >> 5;
    const int lane = tid & 31;

    for (int i = tid; i < 1024; i += 512) {
        const int row = i >> 3, c4 = (i & 7) * 4;
        const int src = row * 128 + rank * 32 + c4;
        const int dst = row * 32 + c4;
        *(float4*)&cr0_s[dst] = *(const float4*)&cr0[src];
        *(float4*)&cz0_s[dst] = *(const float4*)&cz0[src];
        *(float4*)&ch0_s[dst] = *(const float4*)&ch0[src];
    }
    for (int i = tid; i < 4096; i += 512) {
        const int row = i >> 4, c4 = (i & 15) * 4;
        *(float4*)&cr1_s[row * 64 + c4] =
            *(const float4*)&cr1[row * 256 + rank * 64 + c4];
    }
    for (int i = tid; i < 2048; i += 512) {
        const int row = i >> 3, c4 = (i & 7) * 4;
        *(float4*)&cz1_s[row * 32 + c4] =
            *(const float4*)&cz1[row * 128 + rank * 32 + c4];
        *(float4*)&ch1_s[row * 32 + c4] =
            *(const float4*)&ch1[row * 128 + rank * 32 + c4];
    }
    h_s[tid] = 0.0f; h_s[512 + tid] = 0.0f;
    __syncthreads();
    CLUSTER_SYNC();

    uint32_t peer_rh[3], peer_h[3];
    {
        int p = 0;
        for (int r = 0; r < 4; r++) {
            if (r == rank) continue;
            peer_rh[p] = mapa_u32(smem_u32(rh_s), (uint32_t)r);
            peer_h[p]  = mapa_u32(smem_u32(h_s),  (uint32_t)r);
            p++;
        }
    }

    const float* xt  = g_proj;
    const float* xrt = g_proj + (size_t)GM * GN;
    const float* xzt = g_proj + 2ull * GM * GN;

    for (int t = 0; t < SEQ_LEN; t++) {
        const bool aa1 = (t & 1) == 0, aa2 = (t & 3) == 0, aa3 = (t & 7) == 0;
        int act[4]; int na = 0;
        act[na++] = 0;
        if (aa1) act[na++] = 1;
        if (aa2) act[na++] = 2;
        if (aa3) act[na++] = 3;

        const size_t xr0 = ((size_t)(bp * 2 + 0) * SEQ_LEN + t) * GN;
        const size_t xr1 = ((size_t)(bp * 2 + 1) * SEQ_LEN + t) * GN;

        // ============ pass 1: r/z dots → private partial slots ==============
        {
            const int nwt = (aa2 ? 12 : 0) + (aa3 ? 16 : 0);
            for (int wt = wid; wt < nwt; wt += 16) {
                int k = wt;
                float A0[4] = {0,0,0,0}, A1[4] = {0,0,0,0};
                if (aa2 && k < 6) {                       // block2 r (96 cols)
                    const int seg = k;
                    if (lane < 24) {
                        wdot_wide<24>(cr2 + (size_t)(seg * 64) * 384 + rank * 96,
                                      384, h_s + seg * 64, h_s + 512 + seg * 64,
                                      A0, A1, lane);
                        if (seg == 0) {
                            const int j = rank * 96 + lane * 4;
                            float4 B0 = *(const float4*)&xrt[xr0 + j];
                            float4 B1 = *(const float4*)&xrt[xr1 + j];
                            A0[0]+=B0.x; A0[1]+=B0.y; A0[2]+=B0.z; A0[3]+=B0.w;
                            A1[0]+=B1.x; A1[1]+=B1.y; A1[2]+=B1.z; A1[3]+=B1.w;
                        }
                        float* P = rp + c_RPB[2] + (seg * 2) * 96 + lane * 4;
                        *(float4*)P        = make_float4(A0[0],A0[1],A0[2],A0[3]);
                        *(float4*)(P + 96) = make_float4(A1[0],A1[1],A1[2],A1[3]);
                    }
                    continue;
                }
                if (aa2) { k -= 6;
                if (k < 6) {                              // block2 z (32 cols)
                    const int seg = k;
                    wdot_w8(cz2 + (size_t)(seg * 64) * 128 + rank * 32,
                            h_s + seg * 64, h_s + 512 + seg * 64, A0, A1, lane);
                    if (lane < 8) {
                        if (seg == 0) {
                            const int gc = 256 + rank * 32 + lane * 4;
                            float4 B0 = *(const float4*)&xzt[xr0 + gc];
                            float4 B1 = *(const float4*)&xzt[xr1 + gc];
                            A0[0]+=B0.x; A0[1]+=B0.y; A0[2]+=B0.z; A0[3]+=B0.w;
                            A1[0]+=B1.x; A1[1]+=B1.y; A1[2]+=B1.z; A1[3]+=B1.w;
                        }
                        float* P = zp + c_ZPB[2] + (seg * 2) * 32 + lane * 4;
                        *(float4*)P        = make_float4(A0[0],A0[1],A0[2],A0[3]);
                        *(float4*)(P + 32) = make_float4(A1[0],A1[1],A1[2],A1[3]);
                    }
                    continue;
                }
                k -= 6; }
                if (k < 8) {                              // block3 r (128 cols)
                    const int seg = k;
                    wdot_wide<32>(cr3 + (size_t)(seg * 64) * 512 + rank * 128,
                                  512, h_s + seg * 64, h_s + 512 + seg * 64,
                                  A0, A1, lane);
                    if (seg == 0) {
                        const int j = rank * 128 + lane * 4;
                        float4 B0 = *(const float4*)&xrt[xr0 + j];
                        float4 B1 = *(const float4*)&xrt[xr1 + j];
                        A0[0]+=B0.x; A0[1]+=B0.y; A0[2]+=B0.z; A0[3]+=B0.w;
                        A1[0]+=B1.x; A1[1]+=B1.y; A1[2]+=B1.z; A1[3]+=B1.w;
                    }
                    float* P = rp + c_RPB[3] + (seg * 2) * 128 + lane * 4;
                    *(float4*)P         = make_float4(A0[0],A0[1],A0[2],A0[3]);
                    *(float4*)(P + 128) = make_float4(A1[0],A1[1],A1[2],A1[3]);
                } else {                                  // block3 z (32 cols)
                    const int seg = k - 8;
                    wdot_w8(cz3 + (size_t)(seg * 64) * 128 + rank * 32,
                            h_s + seg * 64, h_s + 512 + seg * 64, A0, A1, lane);
                    if (lane < 8) {
                        if (seg == 0) {
                            const int gc = 384 + rank * 32 + lane * 4;
                            float4 B0 = *(const float4*)&xzt[xr0 + gc];
                            float4 B1 = *(const float4*)&xzt[xr1 + gc];
                            A0[0]+=B0.x; A0[1]+=B0.y; A0[2]+=B0.z; A0[3]+=B0.w;
                            A1[0]+=B1.x; A1[1]+=B1.y; A1[2]+=B1.z; A1[3]+=B1.w;
                        }
                        float* P = zp + c_ZPB[3] + (seg * 2) * 32 + lane * 4;
                        *(float4*)P        = make_float4(A0[0],A0[1],A0[2],A0[3]);
                        *(float4*)(P + 32) = make_float4(A1[0],A1[1],A1[2],A1[3]);
                    }
                }
            }
        }
        {
            const int totalT = 128 + (aa1 ? 96 : 0);
            for (int task = tid; task < totalT; task += 512) {
                int tk = task;
                float A0[4] = {0,0,0,0}, A1[4] = {0,0,0,0};
                if (tk < 64) {                       // b0 r
                    const int q = tk & 7, seg = tk >> 3, c = q * 4;
                    dot_s42<16, 32>(cr0_s + seg * 16 * 32 + c,
                                    h_s + seg * 16, h_s + 512 + seg * 16, A0, A1);
                    if (seg == 0) {
                        const int j = rank * 32 + c;
                        float4 B0 = *(const float4*)&xrt[xr0 + j];
                        float4 B1 = *(const float4*)&xrt[xr1 + j];
                        A0[0]+=B0.x; A0[1]+=B0.y; A0[2]+=B0.z; A0[3]+=B0.w;
                        A1[0]+=B1.x; A1[1]+=B1.y; A1[2]+=B1.z; A1[3]+=B1.w;
                    }
                    float* P = rp + (seg * 2) * 32 + c;
                    *(float4*)P        = make_float4(A0[0],A0[1],A0[2],A0[3]);
                    *(float4*)(P + 32) = make_float4(A1[0],A1[1],A1[2],A1[3]);
                } else if ((tk -= 64) < 64) {        // b0 z
                    const int q = tk & 7, seg = tk >> 3, c = q * 4;
                    dot_s42<16, 32>(cz0_s + seg * 16 * 32 + c,
                                    h_s + seg * 16, h_s + 512 + seg * 16, A0, A1);
                    if (seg == 0) {
                        const int gc = rank * 32 + c;
                        float4 B0 = *(const float4*)&xzt[xr0 + gc];
                        float4 B1 = *(const float4*)&xzt[xr1 + gc];
                        A0[0]+=B0.x; A0[1]+=B0.y; A0[2]+=B0.z; A0[3]+=B0.w;
                        A1[0]+=B1.x; A1[1]+=B1.y; A1[2]+=B1.z; A1[3]+=B1.w;
                    }
                    float* P = zp + (seg * 2) * 32 + c;
                    *(float4*)P        = make_float4(A0[0],A0[1],A0[2],A0[3]);
                    *(float4*)(P + 32) = make_float4(A1[0],A1[1],A1[2],A1[3]);
                } else if ((tk -= 64) < 64) {        // b1 r
                    const int q = tk & 15, seg = tk >> 4, c = q * 4;
                    dot_s42<64, 64>(cr1_s + seg * 64 * 64 + c,
                                    h_s + seg * 64, h_s + 512 + seg * 64, A0, A1);
                    if (seg == 0) {
                        const int j = rank * 64 + c;
                        float4 B0 = *(const float4*)&xrt[xr0 + j];
                        float4 B1 = *(const float4*)&xrt[xr1 + j];
                        A0[0]+=B0.x; A0[1]+=B0.y; A0[2]+=B0.z; A0[3]+=B0.w;
                        A1[0]+=B1.x; A1[1]+=B1.y; A1[2]+=B1.z; A1[3]+=B1.w;
                    }
                    float* P = rp + c_RPB[1] + (seg * 2) * 64 + c;
                    *(float4*)P        = make_float4(A0[0],A0[1],A0[2],A0[3]);
                    *(float4*)(P + 64) = make_float4(A1[0],A1[1],A1[2],A1[3]);
                } else {                             // b1 z
                    tk -= 64;
                    const int q = tk & 7, seg = tk >> 3, c = q * 4;
                    dot_s42<64, 32>(cz1_s + seg * 64 * 32 + c,
                                    h_s + seg * 64, h_s + 512 + seg * 64, A0, A1);
                    if (seg == 0) {
                        const int gc = 128 + rank * 32 + c;
                        float4 B0 = *(const float4*)&xzt[xr0 + gc];
                        float4 B1 = *(const float4*)&xzt[xr1 + gc];
                        A0[0]+=B0.x; A0[1]+=B0.y; A0[2]+=B0.z; A0[3]+=B0.w;
                        A1[0]+=B1.x; A1[1]+=B1.y; A1[2]+=B1.z; A1[3]+=B1.w;
                    }
                    float* P = zp + c_ZPB[1] + (seg * 2) * 32 + c;
                    *(float4*)P        = make_float4(A0[0],A0[1],A0[2],A0[3]);
                    *(float4*)(P + 32) = make_float4(A1[0],A1[1],A1[2],A1[3]);
                }
            }
        }
        __syncthreads();

        // ============ pass 2: reduce r, rh = sig(r)*h, exchange =============
        {
            int pcount[4]; int npairs = 0;
            for (int a = 0; a < na; a++) {
                pcount[a] = (act[a] + 1) * 16;
                npairs += pcount[a];
            }
            for (int s = tid; s < 2 * npairs; s += 512) {
                const int row = s & 1;
                int p = s >> 1;
                int i = 0;
                for (int a = 0; a < na; a++) {
                    if (p < pcount[a]) { i = act[a]; break; }
                    p -= pcount[a];
                }
                const int colsP = (i + 1) * 32;
                const int c2 = p * 2;
                const int j = rank * colsP + c2;
                const float* P = rp + c_RPB[i] + row * colsP + c2;
                float s0 = 0.f, s1 = 0.f;
                const int ns = c_SR[i];
                for (int sg = 0; sg < ns; sg++) {
                    s0 += P[(sg * 2) * colsP];
                    s1 += P[(sg * 2) * colsP + 1];
                }
                const float* hh = h_s + row * 512;
                const float v0 = sigmoidf_(s0) * hh[j];
                const float v1 = sigmoidf_(s1) * hh[j + 1];
                const int idx = c_OFF[i] + j;
                rh_s[row * 1280 + idx]     = v0;
                rh_s[row * 1280 + idx + 1] = v1;
                const uint32_t off = (uint32_t)(row * 1280 + idx) * 4u;
                st_cluster_b64(peer_rh[0] + off, v0, v1);
                st_cluster_b64(peer_rh[1] + off, v0, v1);
                st_cluster_b64(peer_rh[2] + off, v0, v1);
            }
        }
        CLUSTER_SYNC();

        // ============ pass 3: hn-dots → private partials =====================
        {
            const int nwh = (aa2 ? 6 : 0) + (aa3 ? 8 : 0);
            for (int wt = wid; wt < nwh; wt += 16) {
                int k = wt;
                float A0[4] = {0,0,0,0}, A1[4] = {0,0,0,0};
                int i, seg;
                const float* base;
                if (aa2 && k < 6) { i = 2; seg = k; base = ch2; }
                else { if (aa2) k -= 6; i = 3; seg = k; base = ch3; }
                wdot_w8(base + (size_t)(seg * 64) * 128 + rank * 32,
                        rh_s + c_OFF[i] + seg * 64,
                        rh_s + 1280 + c_OFF[i] + seg * 64, A0, A1, lane);
                if (lane < 8) {
                    if (seg == 0) {
                        const int gc = (i << 7) + rank * 32 + lane * 4;
                        float4 B0 = *(const float4*)&xt[xr0 + gc];
                        float4 B1 = *(const float4*)&xt[xr1 + gc];
                        A0[0]+=B0.x; A0[1]+=B0.y; A0[2]+=B0.z; A0[3]+=B0.w;
                        A1[0]+=B1.x; A1[1]+=B1.y; A1[2]+=B1.z; A1[3]+=B1.w;
                    }
                    float* P = hp + c_HPB[i] + (seg * 2) * 32 + lane * 4;
                    *(float4*)P        = make_float4(A0[0],A0[1],A0[2],A0[3]);
                    *(float4*)(P + 32) = make_float4(A1[0],A1[1],A1[2],A1[3]);
                }
            }
        }
        {
            const int totalTh = 64 + (aa1 ? 32 : 0);
            for (int task = tid; task < totalTh; task += 512) {
                int tk = task;
                float A0[4] = {0,0,0,0}, A1[4] = {0,0,0,0};
                if (tk < 64) {                       // b0 h
                    const int q = tk & 7, seg = tk >> 3, c = q * 4;
                    dot_s42<16, 32>(ch0_s + seg * 16 * 32 + c,
                                    rh_s + seg * 16, rh_s + 1280 + seg * 16,
                                    A0, A1);
                    if (seg == 0) {
                        const int gc = rank * 32 + c;
                        float4 B0 = *(const float4*)&xt[xr0 + gc];
                        float4 B1 = *(const float4*)&xt[xr1 + gc];
                        A0[0]+=B0.x; A0[1]+=B0.y; A0[2]+=B0.z; A0[3]+=B0.w;
                        A1[0]+=B1.x; A1[1]+=B1.y; A1[2]+=B1.z; A1[3]+=B1.w;
                    }
                    float* P = hp + (seg * 2) * 32 + c;
                    *(float4*)P        = make_float4(A0[0],A0[1],A0[2],A0[3]);
                    *(float4*)(P + 32) = make_float4(A1[0],A1[1],A1[2],A1[3]);
                } else {                             // b1 h
                    tk -= 64;
                    const int q = tk & 7, seg = tk >> 3, c = q * 4;
                    dot_s42<64, 32>(ch1_s + seg * 64 * 32 + c,
                                    rh_s + 128 + seg * 64,
                                    rh_s + 1280 + 128 + seg * 64, A0, A1);
                    if (seg == 0) {
                        const int gc = 128 + rank * 32 + c;
                        float4 B0 = *(const float4*)&xt[xr0 + gc];
                        float4 B1 = *(const float4*)&xt[xr1 + gc];
                        A0[0]+=B0.x; A0[1]+=B0.y; A0[2]+=B0.z; A0[3]+=B0.w;
                        A1[0]+=B1.x; A1[1]+=B1.y; A1[2]+=B1.z; A1[3]+=B1.w;
                    }
                    float* P = hp + c_HPB[1] + (seg * 2) * 32 + c;
                    *(float4*)P        = make_float4(A0[0],A0[1],A0[2],A0[3]);
                    *(float4*)(P + 32) = make_float4(A1[0],A1[1],A1[2],A1[3]);
                }
            }
        }
        __syncthreads();

        // ============ pass 4: reduce z/hn, gate, update h, exchange ==========
        {
            const int npairs = na * 16;
            for (int s = tid; s < 2 * npairs; s += 512) {
                const int row = s & 1;
                const int p = s >> 1;
                const int i = act[p >> 4];
                const int c2 = (p & 15) * 2;
                const int lc = rank * 32 + c2;
                const int gc = (i << 7) + lc;
                const float* Pz = zp + c_ZPB[i] + row * 32 + c2;
                const float* Ph = hp + c_HPB[i] + row * 32 + c2;
                float z0 = 0.f, z1 = 0.f, n0 = 0.f, n1 = 0.f;
                const int nz = c_SZ[i];
                for (int sg = 0; sg < nz; sg++) {
                    z0 += Pz[(sg * 2) * 32];
                    z1 += Pz[(sg * 2) * 32 + 1];
                }
                const int nh = c_SH[i];
                for (int sg = 0; sg < nh; sg++) {
                    n0 += Ph[(sg * 2) * 32];
                    n1 += Ph[(sg * 2) * 32 + 1];
                }
                const float zz0 = sigmoidf_(z0), zz1 = sigmoidf_(z1);
                const float hn0 = sigmoidf_(n0), hn1 = sigmoidf_(n1);
                float* hh = h_s + row * 512;
                const float v0 = zz0 * hn0 + (1.0f - zz0) * hh[gc];
                const float v1 = zz1 * hn1 + (1.0f - zz1) * hh[gc + 1];
                hh[gc] = v0; hh[gc + 1] = v1;
                const uint32_t off = (uint32_t)(row * 512 + gc) * 4u;
                st_cluster_b64(peer_h[0] + off, v0, v1);
                st_cluster_b64(peer_h[1] + off, v0, v1);
                st_cluster_b64(peer_h[2] + off, v0, v1);
            }
        }
        __syncthreads();

        if (tid < 256) {
            const int row = tid >> 7;
            const int idx = tid & 127;
            const int i = idx >> 5, c = idx & 31;
            const int gc = i * 128 + rank * 32 + c;
            const size_t xr = row ? xr1 : xr0;
            out[xr + gc] = h_s[row * 512 + gc];
        }
        CLUSTER_SYNC();
    }
}

// ---------------------------------------------------------------------------
extern "C" void kernel_launch(void* const* d_in, const int* in_sizes, int n_in,
                              void* d_out, int out_size) {
    (void)in_sizes; (void)n_in; (void)out_size;
    const float* x  = (const float*)d_in[0];
    const float* W  = (const float*)d_in[1];
    const float* bb = (const float*)d_in[2];
    const float* Wr = (const float*)d_in[3];
    const float* br = (const float*)d_in[4];
    const float* Wz = (const float*)d_in[5];
    const float* bz = (const float*)d_in[6];
    const float* ch[4]; const float* cr[4]; const float* cz[4];
    for (int i = 0; i < 4; i++) {
        ch[i] = (const float*)d_in[7 + 3 * i + 0];
        cr[i] = (const float*)d_in[7 + 3 * i + 1];
        cz[i] = (const float*)d_in[7 + 3 * i + 2];
    }
    float* out = (float*)d_out;

    // Clockwork-sparse projections: z in {xt,xrt,xzt} x colblock 0..3
    dim3 grid(1, 256, 12);
    gemm3_kernel<<<grid, 256>>>(x, W, bb, Wr, br, Wz, bz);

    size_t smem_bytes = 56192 * sizeof(float);   // 224,768 B
    cudaFuncSetAttribute(scan_kernel,
                         cudaFuncAttributeMaxDynamicSharedMemorySize,
                         (int)smem_bytes);
    scan_kernel<<<(NBATCH / 2) * 4, 512, smem_bytes>>>(
        ch[0], cr[0], cz[0],
        ch[1], cr[1], cz[1],
        ch[2], cr[2], cz[2],
        ch[3], cr[3], cz[3],
        out);
}